// round 14
// baseline (speedup 1.0000x reference)
#include <cuda_runtime.h>
#include <cstdint>

#define BB   32
#define CC   3072
#define HWD  784
#define KK   11
#define NCLS 200
#define NPX  392            // HWD/2, u64 pixel slots per channel row
#define NB1  14             // pixel blocks in k1 (14*28 u64 = 392)
#define CB2  192            // channels per CTA in k2
#define XST2 10             // k2 xs row stride in u64 (conflict-free, 16B-aligned)
#define NQ   4              // pixel quarters in k2

typedef unsigned long long u64;

// ---- scratch (static device memory; no allocations) ----
__device__ float g_asq[KK];
__device__ float g_fsT[CC * BB];            // sum_k afm, transposed [c][b]
__device__ float g_attnp[NB1 * BB * KK];    // attn partials per pixel-block
__device__ ulonglong2 g_wpk[24 * 128 * 6];  // packed k-pair weights, 288 KB
__device__ float g_sp[4 * BB * NCLS];       // score partials per c-quarter
__device__ float g_afp[NQ * BB * CC * KK];  // afm partials per pixel-quarter, 17.3 MB

// ---- packed f32x2 helpers (sm_10x) ----
__device__ __forceinline__ u64 fma2(u64 a, u64 b, u64 c) {
    u64 d; asm("fma.rn.f32x2 %0, %1, %2, %3;" : "=l"(d) : "l"(a), "l"(b), "l"(c)); return d;
}
__device__ __forceinline__ u64 add2(u64 a, u64 b) {
    u64 d; asm("add.rn.f32x2 %0, %1, %2;" : "=l"(d) : "l"(a), "l"(b)); return d;
}
__device__ __forceinline__ u64 pk(float lo, float hi) {
    u64 d; asm("mov.b64 %0, {%1, %2};" : "=l"(d) : "f"(lo), "f"(hi)); return d;
}
__device__ __forceinline__ void upk(u64 v, float& lo, float& hi) {
    asm("mov.b64 {%0, %1}, %2;" : "=f"(lo), "=f"(hi) : "l"(v));
}

// ---- cp.async helpers ----
__device__ __forceinline__ uint32_t smem_u32(const void* p) {
    return (uint32_t)__cvta_generic_to_shared(p);
}
__device__ __forceinline__ void cpa16(uint32_t dst, const void* src) {
    asm volatile("cp.async.cg.shared.global [%0], [%1], 16;" :: "r"(dst), "l"(src));
}
#define CP_COMMIT() asm volatile("cp.async.commit_group;")
#define CP_WAIT1()  asm volatile("cp.async.wait_group 1;")
#define CP_WAIT0()  asm volatile("cp.async.wait_group 0;")

// ================= kernel 0a: a_sq[k] = sum_c w_land[k,c]^2 ================
__global__ void __launch_bounds__(256) k_asq(const float* __restrict__ w_land) {
    const int k = blockIdx.x;                 // 11 blocks
    const float4* wr = (const float4*)(w_land + (size_t)k * CC);
    float s = 0.f;
    for (int i = threadIdx.x; i < CC / 4; i += 256) {
        float4 v = wr[i];
        s += v.x * v.x + v.y * v.y + v.z * v.z + v.w * v.w;
    }
    __shared__ float red[8];
    int lane = threadIdx.x & 31, wid = threadIdx.x >> 5;
    #pragma unroll
    for (int o = 16; o; o >>= 1) s += __shfl_down_sync(0xffffffffu, s, o);
    if (lane == 0) red[wid] = s;
    __syncthreads();
    if (threadIdx.x == 0) {
        float t = 0.f;
        #pragma unroll
        for (int w = 0; w < 8; w++) t += red[w];
        g_asq[k] = t;
    }
}

// ====== kernel 0b: pack weights as k-pair dup u64 pairs, per 128-chunk =====
__global__ void __launch_bounds__(256) k_pack(const float* __restrict__ w_land) {
    const int chunk = blockIdx.x;
    for (int i = threadIdx.x; i < 128 * 6; i += 256) {
        int c = i / 6, kp = i - c * 6;
        int k0 = 2 * kp;
        float w0 = w_land[(size_t)k0 * CC + chunk * 128 + c];
        float w1 = (k0 + 1 < KK) ? w_land[(size_t)(k0 + 1) * CC + chunk * 128 + c] : 0.f;
        ulonglong2 v; v.x = pk(w0, w0); v.y = pk(w1, w1);
        g_wpk[chunk * 768 + i] = v;
    }
}

// ======= kernel 1: fused ab (full-C) + softmax + maps + attn partials ======
__global__ void __launch_bounds__(256, 3) k1(const float* __restrict__ x,
                                             float* __restrict__ out_maps) {
    const int b = blockIdx.y, bx = blockIdx.x;
    const int tid = threadIdx.x, warp = tid >> 5, lane = tid & 31;
    __shared__ ulonglong2 ws2[128 * 6];      // 12 KB, [c][kp]
    __shared__ u64 psum[8 * KK * 28];        // 19.7 KB
    __shared__ float redf[KK * 56];          // 2.46 KB
    __shared__ float smp[KK * 56];           // 2.46 KB

    const int ln = (lane < 28) ? lane : 27;  // clamp inactive lanes
    const int s = bx * 28 + ln;              // u64 pixel slot 0..391
    const u64* xg = (const u64*)x + (size_t)b * CC * NPX + s;

    u64 acc[KK];
    #pragma unroll
    for (int k = 0; k < KK; k++) acc[k] = 0ull;

    for (int chunk = 0; chunk < 24; chunk++) {
        const ulonglong2* wp = g_wpk + chunk * 768;
        ws2[tid]       = wp[tid];
        ws2[tid + 256] = wp[tid + 256];
        ws2[tid + 512] = wp[tid + 512];
        __syncthreads();
        const u64* xc = xg + (size_t)(chunk * 128 + warp * 16) * NPX;
        u64 xa[4], xb[4];
        #pragma unroll
        for (int j = 0; j < 4; j++) xa[j] = xc[(size_t)j * NPX];
        #pragma unroll
        for (int g = 0; g < 4; g++) {
            if (g < 3) {                     // prefetch next batch (MLP 4)
                const u64* xn = xc + (size_t)(4 * (g + 1)) * NPX;
                #pragma unroll
                for (int j = 0; j < 4; j++) xb[j] = xn[(size_t)j * NPX];
            }
            #pragma unroll
            for (int cc = 0; cc < 4; cc++) {
                const ulonglong2* wr = ws2 + (warp * 16 + 4 * g + cc) * 6;
                u64 xv = xa[cc];
                ulonglong2 w0 = wr[0], w1 = wr[1], w2 = wr[2];
                ulonglong2 w3 = wr[3], w4 = wr[4], w5 = wr[5];
                acc[0]  = fma2(xv, w0.x, acc[0]);
                acc[1]  = fma2(xv, w0.y, acc[1]);
                acc[2]  = fma2(xv, w1.x, acc[2]);
                acc[3]  = fma2(xv, w1.y, acc[3]);
                acc[4]  = fma2(xv, w2.x, acc[4]);
                acc[5]  = fma2(xv, w2.y, acc[5]);
                acc[6]  = fma2(xv, w3.x, acc[6]);
                acc[7]  = fma2(xv, w3.y, acc[7]);
                acc[8]  = fma2(xv, w4.x, acc[8]);
                acc[9]  = fma2(xv, w4.y, acc[9]);
                acc[10] = fma2(xv, w5.x, acc[10]);
            }
            if (g < 3) {
                #pragma unroll
                for (int j = 0; j < 4; j++) xa[j] = xb[j];
            }
        }
        __syncthreads();
    }

    // cross-warp reduce
    if (lane < 28) {
        #pragma unroll
        for (int k = 0; k < KK; k++) psum[(warp * KK + k) * 28 + lane] = acc[k];
    }
    __syncthreads();
    for (int i = tid; i < KK * 28; i += 256) {   // 308 slots, 256 threads
        int k = i / 28, sl = i - k * 28;
        u64 v = 0ull;
        #pragma unroll
        for (int w = 0; w < 8; w++) v = add2(v, psum[(w * KK + k) * 28 + sl]);
        float lo, hi; upk(v, lo, hi);
        redf[k * 56 + 2 * sl]     = lo;
        redf[k * 56 + 2 * sl + 1] = hi;
    }
    __syncthreads();
    // softmax over k per pixel (b_sq cancels: logits = 2*ab - a_sq)
    if (tid < 56) {
        float v[KK];
        float m = -1e30f;
        #pragma unroll
        for (int k = 0; k < KK; k++) {
            v[k] = 2.f * redf[k * 56 + tid] - g_asq[k];
            m = fmaxf(m, v[k]);
        }
        float tot = 0.f;
        #pragma unroll
        for (int k = 0; k < KK; k++) { v[k] = __expf(v[k] - m); tot += v[k]; }
        float inv = 1.f / tot;
        #pragma unroll
        for (int k = 0; k < KK; k++) {
            float mp = v[k] * inv;
            out_maps[((size_t)b * KK + k) * HWD + bx * 56 + tid] = mp;
            smp[k * 56 + tid] = mp;
        }
    }
    __syncthreads();
    if (tid < KK) {
        float t = 0.f;
        #pragma unroll 8
        for (int p = 0; p < 56; p++) t += smp[tid * 56 + p];
        g_attnp[(bx * BB + b) * KK + tid] = t;
    }
}

// ===== kernel 2: PARTIAL afm sums over a pixel-quarter ======================
// grid (16, 4, B), block 96, 2 channels/thread, launch_bounds(96,6) via a
// register diet (staging offsets recomputed per stage). Quarters of
// 104/96/96/96 u64 (13/12/12/12 8-u64 cp.async double-buffered stages).
__global__ void __launch_bounds__(96, 6) k2(const float* __restrict__ x,
                                            const float* __restrict__ maps) {
    const int bx = blockIdx.x, q = blockIdx.y, b = blockIdx.z;
    const int tid = threadIdx.x;
    const int c0 = bx * CB2;
    const int qbase = (q == 0) ? 0 : (104 + 96 * (q - 1));   // 0,104,200,296
    const int NST = (q == 0) ? 13 : 12;
    __shared__ alignas(16) u64 xs[2][CB2 * XST2];   // 2 x 15 KB
    __shared__ alignas(16) u64 mm[2][KK * 8];       // 2 x 0.7 KB

    const u64* xg = (const u64*)x + ((size_t)b * CC + c0) * NPX + qbase;
    const u64* mg = (const u64*)maps + (size_t)b * KK * NPX + qbase;

    const uint32_t xsb = smem_u32(&xs[0][0]);
    const uint32_t mmb = smem_u32(&mm[0][0]);
    const uint32_t XSB = (uint32_t)sizeof(xs[0]);
    const uint32_t MSB = (uint32_t)sizeof(mm[0]);

    u64 acc[2 * KK];
    #pragma unroll
    for (int k = 0; k < 2 * KK; k++) acc[k] = 0ull;

    // staging: 192 ch x 4 16B-chunks = 768 chunks; 96 threads -> 8 each.
    // Offsets recomputed per stage (register diet for 6 CTAs/SM).
    const int mk = tid >> 2, mo = tid & 3;   // map staging coords (tid<44)

    // prologue: stage stage-0 into buffer 0
    #pragma unroll
    for (int i = 0; i < 8; i++) {
        int ci = i * 96 + tid;
        int ch = ci >> 2, off = ci & 3;
        cpa16(xsb + (uint32_t)(ch * XST2 + off * 2) * 8, xg + ch * NPX + off * 2);
    }
    if (tid < 44) cpa16(mmb + (uint32_t)(mk * 8 + mo * 2) * 8, mg + mk * NPX + mo * 2);
    CP_COMMIT();

    for (int hc = 0; hc < NST; hc++) {
        const int cur = hc & 1;
        if (hc + 1 < NST) {                  // stage next 8-u64 stage
            const uint32_t db = cur ? 0 : XSB;   // next buf = cur^1
            const uint32_t dm = cur ? 0 : MSB;
            const int p = (hc + 1) * 8;
            #pragma unroll
            for (int i = 0; i < 8; i++) {
                int ci = i * 96 + tid;
                int ch = ci >> 2, off = ci & 3;
                cpa16(xsb + db + (uint32_t)(ch * XST2 + off * 2) * 8,
                      xg + ch * NPX + off * 2 + p);
            }
            if (tid < 44)
                cpa16(mmb + dm + (uint32_t)(mk * 8 + mo * 2) * 8,
                      mg + mk * NPX + mo * 2 + p);
            CP_COMMIT();
            CP_WAIT1();                      // current buf's group done
        } else {
            CP_WAIT0();
        }
        __syncthreads();
        const ulonglong2* xA = (const ulonglong2*)&xs[cur][tid * XST2];
        const ulonglong2* xB = (const ulonglong2*)&xs[cur][(tid + 96) * XST2];
        const u64* mc = mm[cur];
        #pragma unroll
        for (int j2 = 0; j2 < 4; j2++) {
            ulonglong2 va = xA[j2], vb = xB[j2];
            #pragma unroll
            for (int k = 0; k < KK; k++) {
                ulonglong2 mv = *(const ulonglong2*)(mc + k * 8 + j2 * 2);
                acc[k]      = fma2(va.x, mv.x, acc[k]);
                acc[k]      = fma2(va.y, mv.y, acc[k]);
                acc[KK + k] = fma2(vb.x, mv.x, acc[KK + k]);
                acc[KK + k] = fma2(vb.y, mv.y, acc[KK + k]);
            }
        }
        __syncthreads();                     // protect buf before restage
    }

    const int cA = c0 + tid, cB = cA + 96;
    float* pA = g_afp + ((size_t)(q * BB + b) * CC + cA) * KK;
    float* pB = g_afp + ((size_t)(q * BB + b) * CC + cB) * KK;
    #pragma unroll
    for (int k = 0; k < KK; k++) {
        float lo, hi;
        upk(acc[k], lo, hi);      pA[k] = lo + hi;
        upk(acc[KK + k], lo, hi); pB[k] = lo + hi;
    }
}

// ===== kernel 2fin: combine pixel-quarters, modulate, afm + fsT + attn =====
// grid 384, block 256: one (b,c) per thread.
__global__ void __launch_bounds__(256) k2fin(const float* __restrict__ modulation,
                                             float* __restrict__ out_afm,
                                             float* __restrict__ out_attn) {
    const int idx = blockIdx.x * 256 + threadIdx.x;   // 0..98303
    const int b = idx / CC, c = idx - b * CC;
    const float* md = modulation + c * KK;
    float* ao = out_afm + (size_t)idx * KK;
    const float inv = 1.f / 784.f;
    float fs = 0.f;
    #pragma unroll
    for (int k = 0; k < KK; k++) {
        float v = 0.f;
        #pragma unroll
        for (int q = 0; q < NQ; q++)
            v += g_afp[((size_t)q * BB * CC + idx) * KK + k];
        v = v * inv * md[k];
        ao[k] = v;
        fs += v;
    }
    g_fsT[c * BB + b] = fs;
    if (idx < BB * KK) {                     // finish attn (g_attnp from k1)
        int ab = idx / KK, ak = idx - ab * KK;
        float t = 0.f;
        #pragma unroll
        for (int qq = 0; qq < NB1; qq++) t += g_attnp[(qq * BB + ab) * KK + ak];
        out_attn[idx] = t;
    }
}

// ===== kernel 3: score partials over c-quarters =============================
__global__ void __launch_bounds__(128) k_scores(const float* __restrict__ w_cls) {
    const int warp = threadIdx.x >> 5, lane = threadIdx.x & 31;
    const int tid = threadIdx.x;
    const int n0 = blockIdx.x * 4, q = blockIdx.y;
    __shared__ float fsm[256 * BB];           // 32 KB
    __shared__ float4 wsm[4][64];             // 4 KB

    float acc = 0.f;
    for (int ch = 0; ch < 3; ch++) {
        const int cbase = q * 768 + ch * 256;
        __syncthreads();
        const float4* src = (const float4*)(g_fsT + (size_t)cbase * BB);
        float4* dst = (float4*)fsm;
        #pragma unroll
        for (int i = 0; i < 16; i++)          // 2048 float4, coalesced, MLP 16
            dst[i * 128 + tid] = src[i * 128 + tid];
        #pragma unroll
        for (int i = 0; i < 2; i++) {
            int idx = i * 128 + tid;          // 0..255
            int g = idx >> 6, j = idx & 63;
            wsm[g][j] = *((const float4*)(w_cls + (size_t)(n0 + g) * CC + cbase) + j);
        }
        __syncthreads();
        #pragma unroll 8
        for (int j = 0; j < 64; j++) {
            float4 wv = wsm[warp][j];         // broadcast LDS.128
            int c = j * 4;
            acc = fmaf(fsm[(c + 0) * BB + lane], wv.x, acc);
            acc = fmaf(fsm[(c + 1) * BB + lane], wv.y, acc);
            acc = fmaf(fsm[(c + 2) * BB + lane], wv.z, acc);
            acc = fmaf(fsm[(c + 3) * BB + lane], wv.w, acc);
        }
    }
    g_sp[(q * BB + lane) * NCLS + n0 + warp] = acc;
}

// ===== kernel 4: finish scores (sum 4 quarters) ============================
__global__ void __launch_bounds__(256) k_fin(float* __restrict__ out_scores) {
    int i = blockIdx.x * 256 + threadIdx.x;   // 6400 elements, grid 25
    out_scores[i] = (g_sp[i] + g_sp[BB * NCLS + i])
                  + (g_sp[2 * BB * NCLS + i] + g_sp[3 * BB * NCLS + i]);
}

// ============================== launch =====================================
extern "C" void kernel_launch(void* const* d_in, const int* in_sizes, int n_in,
                              void* d_out, int out_size) {
    const float* x          = (const float*)d_in[0];
    const float* w_land     = (const float*)d_in[1];
    const float* modulation = (const float*)d_in[2];
    const float* w_cls      = (const float*)d_in[3];
    float* out        = (float*)d_out;
    float* out_afm    = out;                               // (B,C,K)  1081344
    float* out_scores = out + 1081344;                     // (B,NC)      6400
    float* out_maps   = out + 1087744;                     // (B,K,H,W) 275968
    float* out_attn   = out + 1363712;                     // (B,K)        352

    k_asq<<<KK, 256>>>(w_land);
    k_pack<<<24, 256>>>(w_land);
    k1<<<dim3(NB1, BB), 256>>>(x, out_maps);
    k2<<<dim3(CC / CB2, NQ, BB), 96>>>(x, out_maps);
    k2fin<<<384, 256>>>(modulation, out_afm, out_attn);
    k_scores<<<dim3(50, 4), 128>>>(w_cls);
    k_fin<<<25, 256>>>(out_scores);
}

// round 15
// speedup vs baseline: 1.0506x; 1.0506x over previous
#include <cuda_runtime.h>
#include <cstdint>

#define BB   32
#define CC   3072
#define HWD  784
#define KK   11
#define NCLS 200
#define NPX  392            // HWD/2, u64 pixel slots per channel row
#define NB1  14             // pixel blocks in k1 (14*28 u64 = 392)
#define CB2  192            // channels per CTA in k2
#define XST2 10             // k2 xs row stride in u64 (conflict-free, 16B-aligned)
#define NQ   2              // pixel halves in k2

typedef unsigned long long u64;

// ---- scratch (static device memory; no allocations) ----
__device__ float g_asq[KK];
__device__ float g_fsT[CC * BB];            // sum_k afm, transposed [c][b]
__device__ float g_attnp[NB1 * BB * KK];    // attn partials per pixel-block
__device__ ulonglong2 g_wpk[24 * 128 * 6];  // packed k-pair weights, 288 KB
__device__ float g_sp[4 * BB * NCLS];       // score partials per c-quarter
__device__ float g_afp[NQ * BB * CC * KK];  // afm partials per pixel-half, 8.7 MB

// ---- packed f32x2 helpers (sm_10x) ----
__device__ __forceinline__ u64 fma2(u64 a, u64 b, u64 c) {
    u64 d; asm("fma.rn.f32x2 %0, %1, %2, %3;" : "=l"(d) : "l"(a), "l"(b), "l"(c)); return d;
}
__device__ __forceinline__ u64 add2(u64 a, u64 b) {
    u64 d; asm("add.rn.f32x2 %0, %1, %2;" : "=l"(d) : "l"(a), "l"(b)); return d;
}
__device__ __forceinline__ u64 pk(float lo, float hi) {
    u64 d; asm("mov.b64 %0, {%1, %2};" : "=l"(d) : "f"(lo), "f"(hi)); return d;
}
__device__ __forceinline__ void upk(u64 v, float& lo, float& hi) {
    asm("mov.b64 {%0, %1}, %2;" : "=f"(lo), "=f"(hi) : "l"(v));
}

// ---- cp.async helpers ----
__device__ __forceinline__ uint32_t smem_u32(const void* p) {
    return (uint32_t)__cvta_generic_to_shared(p);
}
__device__ __forceinline__ void cpa16(uint32_t dst, const void* src) {
    asm volatile("cp.async.cg.shared.global [%0], [%1], 16;" :: "r"(dst), "l"(src));
}
#define CP_COMMIT() asm volatile("cp.async.commit_group;")
#define CP_WAIT1()  asm volatile("cp.async.wait_group 1;")
#define CP_WAIT0()  asm volatile("cp.async.wait_group 0;")

// ================= kernel 0a: a_sq[k] = sum_c w_land[k,c]^2 ================
__global__ void __launch_bounds__(256) k_asq(const float* __restrict__ w_land) {
    const int k = blockIdx.x;                 // 11 blocks
    const float4* wr = (const float4*)(w_land + (size_t)k * CC);
    float s = 0.f;
    for (int i = threadIdx.x; i < CC / 4; i += 256) {
        float4 v = wr[i];
        s += v.x * v.x + v.y * v.y + v.z * v.z + v.w * v.w;
    }
    __shared__ float red[8];
    int lane = threadIdx.x & 31, wid = threadIdx.x >> 5;
    #pragma unroll
    for (int o = 16; o; o >>= 1) s += __shfl_down_sync(0xffffffffu, s, o);
    if (lane == 0) red[wid] = s;
    __syncthreads();
    if (threadIdx.x == 0) {
        float t = 0.f;
        #pragma unroll
        for (int w = 0; w < 8; w++) t += red[w];
        g_asq[k] = t;
    }
}

// ====== kernel 0b: pack weights as k-pair dup u64 pairs, per 128-chunk =====
__global__ void __launch_bounds__(256) k_pack(const float* __restrict__ w_land) {
    const int chunk = blockIdx.x;
    for (int i = threadIdx.x; i < 128 * 6; i += 256) {
        int c = i / 6, kp = i - c * 6;
        int k0 = 2 * kp;
        float w0 = w_land[(size_t)k0 * CC + chunk * 128 + c];
        float w1 = (k0 + 1 < KK) ? w_land[(size_t)(k0 + 1) * CC + chunk * 128 + c] : 0.f;
        ulonglong2 v; v.x = pk(w0, w0); v.y = pk(w1, w1);
        g_wpk[chunk * 768 + i] = v;
    }
}

// ======= kernel 1: fused ab (full-C) + softmax + maps + attn partials ======
// grid (14, B), block 256. Weights cp.async double-buffered (chunk+1 staged
// while chunk computes); x direct-LDG with MLP-4 register prefetch.
__global__ void __launch_bounds__(256, 3) k1(const float* __restrict__ x,
                                             float* __restrict__ out_maps) {
    const int b = blockIdx.y, bx = blockIdx.x;
    const int tid = threadIdx.x, warp = tid >> 5, lane = tid & 31;
    __shared__ alignas(16) ulonglong2 ws2[2][768];   // 2 x 12 KB
    __shared__ u64 psum[8 * KK * 28];        // 19.7 KB
    __shared__ float redf[KK * 56];          // 2.46 KB
    __shared__ float smp[KK * 56];           // 2.46 KB

    const int ln = (lane < 28) ? lane : 27;  // clamp inactive lanes
    const int s = bx * 28 + ln;              // u64 pixel slot 0..391
    const u64* xg = (const u64*)x + (size_t)b * CC * NPX + s;

    const uint32_t wsb = smem_u32(&ws2[0][0]);
    const uint32_t WSB = (uint32_t)sizeof(ws2[0]);

    u64 acc[KK];
    #pragma unroll
    for (int k = 0; k < KK; k++) acc[k] = 0ull;

    // prologue: stage weights chunk 0 into buffer 0
    #pragma unroll
    for (int j = 0; j < 3; j++) {
        int wi = j * 256 + tid;
        cpa16(wsb + (uint32_t)wi * 16, g_wpk + wi);
    }
    CP_COMMIT();

    for (int chunk = 0; chunk < 24; chunk++) {
        if (chunk + 1 < 24) {                // stage next chunk's weights
            const ulonglong2* wsrc = g_wpk + (chunk + 1) * 768;
            const uint32_t db = (uint32_t)((chunk + 1) & 1) * WSB;
            #pragma unroll
            for (int j = 0; j < 3; j++) {
                int wi = j * 256 + tid;
                cpa16(wsb + db + (uint32_t)wi * 16, wsrc + wi);
            }
            CP_COMMIT();
            CP_WAIT1();                      // current chunk's weights ready
        } else {
            CP_WAIT0();
        }
        __syncthreads();
        const ulonglong2* wcur = ws2[chunk & 1];
        const u64* xc = xg + (size_t)(chunk * 128 + warp * 16) * NPX;
        u64 xa[4], xb[4];
        #pragma unroll
        for (int j = 0; j < 4; j++) xa[j] = xc[(size_t)j * NPX];
        #pragma unroll
        for (int g = 0; g < 4; g++) {
            if (g < 3) {                     // prefetch next batch (MLP 4)
                const u64* xn = xc + (size_t)(4 * (g + 1)) * NPX;
                #pragma unroll
                for (int j = 0; j < 4; j++) xb[j] = xn[(size_t)j * NPX];
            }
            #pragma unroll
            for (int cc = 0; cc < 4; cc++) {
                const ulonglong2* wr = wcur + (warp * 16 + 4 * g + cc) * 6;
                u64 xv = xa[cc];
                ulonglong2 w0 = wr[0], w1 = wr[1], w2 = wr[2];
                ulonglong2 w3 = wr[3], w4 = wr[4], w5 = wr[5];
                acc[0]  = fma2(xv, w0.x, acc[0]);
                acc[1]  = fma2(xv, w0.y, acc[1]);
                acc[2]  = fma2(xv, w1.x, acc[2]);
                acc[3]  = fma2(xv, w1.y, acc[3]);
                acc[4]  = fma2(xv, w2.x, acc[4]);
                acc[5]  = fma2(xv, w2.y, acc[5]);
                acc[6]  = fma2(xv, w3.x, acc[6]);
                acc[7]  = fma2(xv, w3.y, acc[7]);
                acc[8]  = fma2(xv, w4.x, acc[8]);
                acc[9]  = fma2(xv, w4.y, acc[9]);
                acc[10] = fma2(xv, w5.x, acc[10]);
            }
            if (g < 3) {
                #pragma unroll
                for (int j = 0; j < 4; j++) xa[j] = xb[j];
            }
        }
        __syncthreads();                     // protect buffer before restage
    }

    // cross-warp reduce
    if (lane < 28) {
        #pragma unroll
        for (int k = 0; k < KK; k++) psum[(warp * KK + k) * 28 + lane] = acc[k];
    }
    __syncthreads();
    for (int i = tid; i < KK * 28; i += 256) {   // 308 slots, 256 threads
        int k = i / 28, sl = i - k * 28;
        u64 v = 0ull;
        #pragma unroll
        for (int w = 0; w < 8; w++) v = add2(v, psum[(w * KK + k) * 28 + sl]);
        float lo, hi; upk(v, lo, hi);
        redf[k * 56 + 2 * sl]     = lo;
        redf[k * 56 + 2 * sl + 1] = hi;
    }
    __syncthreads();
    // softmax over k per pixel (b_sq cancels: logits = 2*ab - a_sq)
    if (tid < 56) {
        float v[KK];
        float m = -1e30f;
        #pragma unroll
        for (int k = 0; k < KK; k++) {
            v[k] = 2.f * redf[k * 56 + tid] - g_asq[k];
            m = fmaxf(m, v[k]);
        }
        float tot = 0.f;
        #pragma unroll
        for (int k = 0; k < KK; k++) { v[k] = __expf(v[k] - m); tot += v[k]; }
        float inv = 1.f / tot;
        #pragma unroll
        for (int k = 0; k < KK; k++) {
            float mp = v[k] * inv;
            out_maps[((size_t)b * KK + k) * HWD + bx * 56 + tid] = mp;
            smp[k * 56 + tid] = mp;
        }
    }
    __syncthreads();
    if (tid < KK) {
        float t = 0.f;
        #pragma unroll 8
        for (int p = 0; p < 56; p++) t += smp[tid * 56 + p];
        g_attnp[(bx * BB + b) * KK + tid] = t;
    }
}

// ===== kernel 2: PARTIAL afm sums over a pixel-half =========================
// grid (16, 2, B), block 96, 2 channels/thread, launch_bounds(96,6) with
// register diet (staging offsets recomputed per stage). Halves of 200/192
// u64 (25/24 8-u64 cp.async double-buffered stages).
__global__ void __launch_bounds__(96, 6) k2(const float* __restrict__ x,
                                            const float* __restrict__ maps) {
    const int bx = blockIdx.x, q = blockIdx.y, b = blockIdx.z;
    const int tid = threadIdx.x;
    const int c0 = bx * CB2;
    const int qbase = q * 200;               // 0, 200
    const int NST = q ? 24 : 25;
    __shared__ alignas(16) u64 xs[2][CB2 * XST2];   // 2 x 15 KB
    __shared__ alignas(16) u64 mm[2][KK * 8];       // 2 x 0.7 KB

    const u64* xg = (const u64*)x + ((size_t)b * CC + c0) * NPX + qbase;
    const u64* mg = (const u64*)maps + (size_t)b * KK * NPX + qbase;

    const uint32_t xsb = smem_u32(&xs[0][0]);
    const uint32_t mmb = smem_u32(&mm[0][0]);
    const uint32_t XSB = (uint32_t)sizeof(xs[0]);
    const uint32_t MSB = (uint32_t)sizeof(mm[0]);

    u64 acc[2 * KK];
    #pragma unroll
    for (int k = 0; k < 2 * KK; k++) acc[k] = 0ull;

    const int mk = tid >> 2, mo = tid & 3;   // map staging coords (tid<44)

    // prologue: stage stage-0 into buffer 0
    #pragma unroll
    for (int i = 0; i < 8; i++) {
        int ci = i * 96 + tid;
        int ch = ci >> 2, off = ci & 3;
        cpa16(xsb + (uint32_t)(ch * XST2 + off * 2) * 8, xg + ch * NPX + off * 2);
    }
    if (tid < 44) cpa16(mmb + (uint32_t)(mk * 8 + mo * 2) * 8, mg + mk * NPX + mo * 2);
    CP_COMMIT();

    for (int hc = 0; hc < NST; hc++) {
        const int cur = hc & 1;
        if (hc + 1 < NST) {                  // stage next 8-u64 stage
            const uint32_t db = cur ? 0 : XSB;   // next buf = cur^1
            const uint32_t dm = cur ? 0 : MSB;
            const int p = (hc + 1) * 8;
            #pragma unroll
            for (int i = 0; i < 8; i++) {
                int ci = i * 96 + tid;
                int ch = ci >> 2, off = ci & 3;
                cpa16(xsb + db + (uint32_t)(ch * XST2 + off * 2) * 8,
                      xg + ch * NPX + off * 2 + p);
            }
            if (tid < 44)
                cpa16(mmb + dm + (uint32_t)(mk * 8 + mo * 2) * 8,
                      mg + mk * NPX + mo * 2 + p);
            CP_COMMIT();
            CP_WAIT1();                      // current buf's group done
        } else {
            CP_WAIT0();
        }
        __syncthreads();
        const ulonglong2* xA = (const ulonglong2*)&xs[cur][tid * XST2];
        const ulonglong2* xB = (const ulonglong2*)&xs[cur][(tid + 96) * XST2];
        const u64* mc = mm[cur];
        #pragma unroll
        for (int j2 = 0; j2 < 4; j2++) {
            ulonglong2 va = xA[j2], vb = xB[j2];
            #pragma unroll
            for (int k = 0; k < KK; k++) {
                ulonglong2 mv = *(const ulonglong2*)(mc + k * 8 + j2 * 2);
                acc[k]      = fma2(va.x, mv.x, acc[k]);
                acc[k]      = fma2(va.y, mv.y, acc[k]);
                acc[KK + k] = fma2(vb.x, mv.x, acc[KK + k]);
                acc[KK + k] = fma2(vb.y, mv.y, acc[KK + k]);
            }
        }
        __syncthreads();                     // protect buf before restage
    }

    const int cA = c0 + tid, cB = cA + 96;
    float* pA = g_afp + ((size_t)(q * BB + b) * CC + cA) * KK;
    float* pB = g_afp + ((size_t)(q * BB + b) * CC + cB) * KK;
    #pragma unroll
    for (int k = 0; k < KK; k++) {
        float lo, hi;
        upk(acc[k], lo, hi);      pA[k] = lo + hi;
        upk(acc[KK + k], lo, hi); pB[k] = lo + hi;
    }
}

// ===== kernel 2fin: combine pixel-halves, modulate, afm + fsT + attn =======
// grid 384, block 256: one (b,c) per thread.
__global__ void __launch_bounds__(256) k2fin(const float* __restrict__ modulation,
                                             float* __restrict__ out_afm,
                                             float* __restrict__ out_attn) {
    const int idx = blockIdx.x * 256 + threadIdx.x;   // 0..98303
    const int b = idx / CC, c = idx - b * CC;
    const float* p0 = g_afp + (size_t)idx * KK;
    const float* p1 = g_afp + ((size_t)BB * CC + idx) * KK;
    const float* md = modulation + c * KK;
    float* ao = out_afm + (size_t)idx * KK;
    const float inv = 1.f / 784.f;
    float fs = 0.f;
    #pragma unroll
    for (int k = 0; k < KK; k++) {
        float v = (p0[k] + p1[k]) * inv * md[k];
        ao[k] = v;
        fs += v;
    }
    g_fsT[c * BB + b] = fs;
    if (idx < BB * KK) {                     // finish attn (g_attnp from k1)
        int ab = idx / KK, ak = idx - ab * KK;
        float t = 0.f;
        #pragma unroll
        for (int qq = 0; qq < NB1; qq++) t += g_attnp[(qq * BB + ab) * KK + ak];
        out_attn[idx] = t;
    }
}

// ===== kernel 3: score partials over c-quarters =============================
__global__ void __launch_bounds__(128) k_scores(const float* __restrict__ w_cls) {
    const int warp = threadIdx.x >> 5, lane = threadIdx.x & 31;
    const int tid = threadIdx.x;
    const int n0 = blockIdx.x * 4, q = blockIdx.y;
    __shared__ float fsm[256 * BB];           // 32 KB
    __shared__ float4 wsm[4][64];             // 4 KB

    float acc = 0.f;
    for (int ch = 0; ch < 3; ch++) {
        const int cbase = q * 768 + ch * 256;
        __syncthreads();
        const float4* src = (const float4*)(g_fsT + (size_t)cbase * BB);
        float4* dst = (float4*)fsm;
        #pragma unroll
        for (int i = 0; i < 16; i++)          // 2048 float4, coalesced, MLP 16
            dst[i * 128 + tid] = src[i * 128 + tid];
        #pragma unroll
        for (int i = 0; i < 2; i++) {
            int idx = i * 128 + tid;          // 0..255
            int g = idx >> 6, j = idx & 63;
            wsm[g][j] = *((const float4*)(w_cls + (size_t)(n0 + g) * CC + cbase) + j);
        }
        __syncthreads();
        #pragma unroll 8
        for (int j = 0; j < 64; j++) {
            float4 wv = wsm[warp][j];         // broadcast LDS.128
            int c = j * 4;
            acc = fmaf(fsm[(c + 0) * BB + lane], wv.x, acc);
            acc = fmaf(fsm[(c + 1) * BB + lane], wv.y, acc);
            acc = fmaf(fsm[(c + 2) * BB + lane], wv.z, acc);
            acc = fmaf(fsm[(c + 3) * BB + lane], wv.w, acc);
        }
    }
    g_sp[(q * BB + lane) * NCLS + n0 + warp] = acc;
}

// ===== kernel 4: finish scores (sum 4 quarters) ============================
__global__ void __launch_bounds__(256) k_fin(float* __restrict__ out_scores) {
    int i = blockIdx.x * 256 + threadIdx.x;   // 6400 elements, grid 25
    out_scores[i] = (g_sp[i] + g_sp[BB * NCLS + i])
                  + (g_sp[2 * BB * NCLS + i] + g_sp[3 * BB * NCLS + i]);
}

// ============================== launch =====================================
extern "C" void kernel_launch(void* const* d_in, const int* in_sizes, int n_in,
                              void* d_out, int out_size) {
    const float* x          = (const float*)d_in[0];
    const float* w_land     = (const float*)d_in[1];
    const float* modulation = (const float*)d_in[2];
    const float* w_cls      = (const float*)d_in[3];
    float* out        = (float*)d_out;
    float* out_afm    = out;                               // (B,C,K)  1081344
    float* out_scores = out + 1081344;                     // (B,NC)      6400
    float* out_maps   = out + 1087744;                     // (B,K,H,W) 275968
    float* out_attn   = out + 1363712;                     // (B,K)        352

    k_asq<<<KK, 256>>>(w_land);
    k_pack<<<24, 256>>>(w_land);
    k1<<<dim3(NB1, BB), 256>>>(x, out_maps);
    k2<<<dim3(CC / CB2, NQ, BB), 96>>>(x, out_maps);
    k2fin<<<384, 256>>>(modulation, out_afm, out_attn);
    k_scores<<<dim3(50, 4), 128>>>(w_cls);
    k_fin<<<25, 256>>>(out_scores);
}

// round 16
// speedup vs baseline: 1.0873x; 1.0349x over previous
#include <cuda_runtime.h>
#include <cstdint>

#define BB   32
#define CC   3072
#define HWD  784
#define KK   11
#define NCLS 200
#define NPX  392            // HWD/2, u64 pixel slots per channel row
#define NB1  14             // pixel blocks in k1 (14*28 u64 = 392)
#define CB2  192            // channels per CTA in k2
#define XST2 10             // k2 xs row stride in u64 (conflict-free, 16B-aligned)
#define NQ   2              // pixel halves in k2

typedef unsigned long long u64;

// ---- scratch (static device memory; no allocations) ----
__device__ float g_asq[KK];
__device__ float g_fsT[CC * BB];            // sum_k afm, transposed [c][b]
__device__ float g_attnp[NB1 * BB * KK];    // attn partials per pixel-block
__device__ ulonglong2 g_wpk[24 * 128 * 6];  // packed k-pair weights, 288 KB
__device__ float g_sp[4 * BB * NCLS];       // score partials per c-quarter
__device__ float g_afp[NQ * BB * CC * KK];  // afm partials per pixel-half, 8.7 MB

// ---- packed f32x2 helpers (sm_10x) ----
__device__ __forceinline__ u64 fma2(u64 a, u64 b, u64 c) {
    u64 d; asm("fma.rn.f32x2 %0, %1, %2, %3;" : "=l"(d) : "l"(a), "l"(b), "l"(c)); return d;
}
__device__ __forceinline__ u64 add2(u64 a, u64 b) {
    u64 d; asm("add.rn.f32x2 %0, %1, %2;" : "=l"(d) : "l"(a), "l"(b)); return d;
}
__device__ __forceinline__ u64 pk(float lo, float hi) {
    u64 d; asm("mov.b64 %0, {%1, %2};" : "=l"(d) : "f"(lo), "f"(hi)); return d;
}
__device__ __forceinline__ void upk(u64 v, float& lo, float& hi) {
    asm("mov.b64 {%0, %1}, %2;" : "=f"(lo), "=f"(hi) : "l"(v));
}

// ---- cp.async helpers ----
__device__ __forceinline__ uint32_t smem_u32(const void* p) {
    return (uint32_t)__cvta_generic_to_shared(p);
}
__device__ __forceinline__ void cpa16(uint32_t dst, const void* src) {
    asm volatile("cp.async.cg.shared.global [%0], [%1], 16;" :: "r"(dst), "l"(src));
}
#define CP_COMMIT() asm volatile("cp.async.commit_group;")
#define CP_WAIT2()  asm volatile("cp.async.wait_group 2;")
#define CP_WAIT1()  asm volatile("cp.async.wait_group 1;")
#define CP_WAIT0()  asm volatile("cp.async.wait_group 0;")

// ================= kernel 0a: a_sq[k] = sum_c w_land[k,c]^2 ================
__global__ void __launch_bounds__(256) k_asq(const float* __restrict__ w_land) {
    const int k = blockIdx.x;                 // 11 blocks
    const float4* wr = (const float4*)(w_land + (size_t)k * CC);
    float s = 0.f;
    for (int i = threadIdx.x; i < CC / 4; i += 256) {
        float4 v = wr[i];
        s += v.x * v.x + v.y * v.y + v.z * v.z + v.w * v.w;
    }
    __shared__ float red[8];
    int lane = threadIdx.x & 31, wid = threadIdx.x >> 5;
    #pragma unroll
    for (int o = 16; o; o >>= 1) s += __shfl_down_sync(0xffffffffu, s, o);
    if (lane == 0) red[wid] = s;
    __syncthreads();
    if (threadIdx.x == 0) {
        float t = 0.f;
        #pragma unroll
        for (int w = 0; w < 8; w++) t += red[w];
        g_asq[k] = t;
    }
}

// ====== kernel 0b: pack weights as k-pair dup u64 pairs, per 128-chunk =====
__global__ void __launch_bounds__(256) k_pack(const float* __restrict__ w_land) {
    const int chunk = blockIdx.x;
    for (int i = threadIdx.x; i < 128 * 6; i += 256) {
        int c = i / 6, kp = i - c * 6;
        int k0 = 2 * kp;
        float w0 = w_land[(size_t)k0 * CC + chunk * 128 + c];
        float w1 = (k0 + 1 < KK) ? w_land[(size_t)(k0 + 1) * CC + chunk * 128 + c] : 0.f;
        ulonglong2 v; v.x = pk(w0, w0); v.y = pk(w1, w1);
        g_wpk[chunk * 768 + i] = v;
    }
}

// ======= kernel 1: fused ab (full-C) + softmax + maps + attn partials ======
// grid (14, B), block 256. Weights cp.async double-buffered; x direct-LDG
// with distance-2 group prefetch (MLP 8) via 3 rotating register buffers.
// Chunks processed in triples so all buffer indices stay compile-time.
__global__ void __launch_bounds__(256, 3) k1(const float* __restrict__ x,
                                             float* __restrict__ out_maps) {
    const int b = blockIdx.y, bx = blockIdx.x;
    const int tid = threadIdx.x, warp = tid >> 5, lane = tid & 31;
    __shared__ alignas(16) ulonglong2 ws2[2][768];   // 2 x 12 KB
    __shared__ u64 psum[8 * KK * 28];        // 19.7 KB
    __shared__ float redf[KK * 56];          // 2.46 KB
    __shared__ float smp[KK * 56];           // 2.46 KB

    const int ln = (lane < 28) ? lane : 27;  // clamp inactive lanes
    const int s = bx * 28 + ln;              // u64 pixel slot 0..391
    const u64* xg = (const u64*)x + (size_t)b * CC * NPX + s;

    const uint32_t wsb = smem_u32(&ws2[0][0]);
    const uint32_t WSB = (uint32_t)sizeof(ws2[0]);

    u64 acc[KK];
    #pragma unroll
    for (int k = 0; k < KK; k++) acc[k] = 0ull;

    // x prefetch prologue: groups 0,1 -> buffers 0,1
    u64 xr[3][4];
    {
        const u64* p = xg + (size_t)(warp * 16) * NPX;
        #pragma unroll
        for (int j = 0; j < 4; j++) xr[0][j] = p[(size_t)j * NPX];
        p += (size_t)4 * NPX;
        #pragma unroll
        for (int j = 0; j < 4; j++) xr[1][j] = p[(size_t)j * NPX];
    }

    // weights prologue: stage chunk 0 into buffer 0
    #pragma unroll
    for (int j = 0; j < 3; j++) {
        int wi = j * 256 + tid;
        cpa16(wsb + (uint32_t)wi * 16, g_wpk + wi);
    }
    CP_COMMIT();

    for (int sc = 0; sc < 8; sc++) {
        #pragma unroll
        for (int c3 = 0; c3 < 3; c3++) {
            const int chunk = sc * 3 + c3;
            if (chunk + 1 < 24) {            // stage next chunk's weights
                const ulonglong2* wsrc = g_wpk + (chunk + 1) * 768;
                const uint32_t db = (uint32_t)((chunk + 1) & 1) * WSB;
                #pragma unroll
                for (int j = 0; j < 3; j++) {
                    int wi = j * 256 + tid;
                    cpa16(wsb + db + (uint32_t)wi * 16, wsrc + wi);
                }
                CP_COMMIT();
                CP_WAIT1();                  // current chunk's weights ready
            } else {
                CP_WAIT0();
            }
            __syncthreads();
            const ulonglong2* wcur = ws2[chunk & 1];
            #pragma unroll
            for (int g = 0; g < 4; g++) {
                const int bufc = (c3 * 4 + g) % 3;       // compile-time
                const int bufn = (c3 * 4 + g + 2) % 3;   // compile-time
                const int pg = chunk * 4 + g + 2;        // prefetch group
                if (pg < 96) {
                    const int pch = (pg >> 2) * 128 + warp * 16 + (pg & 3) * 4;
                    const u64* xn = xg + (size_t)pch * NPX;
                    #pragma unroll
                    for (int j = 0; j < 4; j++) xr[bufn][j] = xn[(size_t)j * NPX];
                }
                const ulonglong2* wr0 = wcur + (warp * 16 + g * 4) * 6;
                #pragma unroll
                for (int cc = 0; cc < 4; cc++) {
                    u64 xv = xr[bufc][cc];
                    const ulonglong2* wr = wr0 + cc * 6;
                    ulonglong2 w0 = wr[0], w1 = wr[1], w2 = wr[2];
                    ulonglong2 w3 = wr[3], w4 = wr[4], w5 = wr[5];
                    acc[0]  = fma2(xv, w0.x, acc[0]);
                    acc[1]  = fma2(xv, w0.y, acc[1]);
                    acc[2]  = fma2(xv, w1.x, acc[2]);
                    acc[3]  = fma2(xv, w1.y, acc[3]);
                    acc[4]  = fma2(xv, w2.x, acc[4]);
                    acc[5]  = fma2(xv, w2.y, acc[5]);
                    acc[6]  = fma2(xv, w3.x, acc[6]);
                    acc[7]  = fma2(xv, w3.y, acc[7]);
                    acc[8]  = fma2(xv, w4.x, acc[8]);
                    acc[9]  = fma2(xv, w4.y, acc[9]);
                    acc[10] = fma2(xv, w5.x, acc[10]);
                }
            }
            __syncthreads();                 // protect weight buffer
        }
    }

    // cross-warp reduce
    if (lane < 28) {
        #pragma unroll
        for (int k = 0; k < KK; k++) psum[(warp * KK + k) * 28 + lane] = acc[k];
    }
    __syncthreads();
    for (int i = tid; i < KK * 28; i += 256) {   // 308 slots, 256 threads
        int k = i / 28, sl = i - k * 28;
        u64 v = 0ull;
        #pragma unroll
        for (int w = 0; w < 8; w++) v = add2(v, psum[(w * KK + k) * 28 + sl]);
        float lo, hi; upk(v, lo, hi);
        redf[k * 56 + 2 * sl]     = lo;
        redf[k * 56 + 2 * sl + 1] = hi;
    }
    __syncthreads();
    // softmax over k per pixel (b_sq cancels: logits = 2*ab - a_sq)
    if (tid < 56) {
        float v[KK];
        float m = -1e30f;
        #pragma unroll
        for (int k = 0; k < KK; k++) {
            v[k] = 2.f * redf[k * 56 + tid] - g_asq[k];
            m = fmaxf(m, v[k]);
        }
        float tot = 0.f;
        #pragma unroll
        for (int k = 0; k < KK; k++) { v[k] = __expf(v[k] - m); tot += v[k]; }
        float inv = 1.f / tot;
        #pragma unroll
        for (int k = 0; k < KK; k++) {
            float mp = v[k] * inv;
            out_maps[((size_t)b * KK + k) * HWD + bx * 56 + tid] = mp;
            smp[k * 56 + tid] = mp;
        }
    }
    __syncthreads();
    if (tid < KK) {
        float t = 0.f;
        #pragma unroll 8
        for (int p = 0; p < 56; p++) t += smp[tid * 56 + p];
        g_attnp[(bx * BB + b) * KK + tid] = t;
    }
}

// ===== kernel 2: PARTIAL afm sums over a pixel-half =========================
// grid (16, 2, B), block 96, 2 channels/thread. TRIPLE-buffered cp.async
// pipeline (depth 2 in flight) — stage hc+2 while computing hc; wait_group 2.
// smem 48.2 KB -> 4 CTAs/SM. Halves of 200/192 u64 (25/24 8-u64 stages).
__global__ void __launch_bounds__(96, 4) k2(const float* __restrict__ x,
                                            const float* __restrict__ maps) {
    const int bx = blockIdx.x, q = blockIdx.y, b = blockIdx.z;
    const int tid = threadIdx.x;
    const int c0 = bx * CB2;
    const int qbase = q * 200;               // 0, 200
    const int NST = q ? 24 : 25;
    __shared__ alignas(16) u64 xs[3][CB2 * XST2];   // 3 x 15 KB
    __shared__ alignas(16) u64 mm[3][KK * 8];       // 3 x 0.7 KB

    const u64* xg = (const u64*)x + ((size_t)b * CC + c0) * NPX + qbase;
    const u64* mg = (const u64*)maps + (size_t)b * KK * NPX + qbase;

    const uint32_t xsb = smem_u32(&xs[0][0]);
    const uint32_t mmb = smem_u32(&mm[0][0]);
    const uint32_t XSB = (uint32_t)sizeof(xs[0]);
    const uint32_t MSB = (uint32_t)sizeof(mm[0]);

    u64 acc[2 * KK];
    #pragma unroll
    for (int k = 0; k < 2 * KK; k++) acc[k] = 0ull;

    const int mk = tid >> 2, mo = tid & 3;   // map staging coords (tid<44)

    // prologue: stage stages 0,1 into buffers 0,1 (two commit groups)
    #pragma unroll
    for (int st = 0; st < 2; st++) {
        const uint32_t db = (uint32_t)st * XSB;
        const uint32_t dm = (uint32_t)st * MSB;
        const int p = st * 8;
        #pragma unroll
        for (int i = 0; i < 8; i++) {
            int ci = i * 96 + tid;
            int ch = ci >> 2, off = ci & 3;
            cpa16(xsb + db + (uint32_t)(ch * XST2 + off * 2) * 8,
                  xg + ch * NPX + off * 2 + p);
        }
        if (tid < 44)
            cpa16(mmb + dm + (uint32_t)(mk * 8 + mo * 2) * 8,
                  mg + mk * NPX + mo * 2 + p);
        CP_COMMIT();
    }

    int cur = 0, stg = 2;
    for (int hc = 0; hc < NST; hc++) {
        if (hc + 2 < NST) {                  // stage stage hc+2
            const uint32_t db = (uint32_t)stg * XSB;
            const uint32_t dm = (uint32_t)stg * MSB;
            const int p = (hc + 2) * 8;
            #pragma unroll
            for (int i = 0; i < 8; i++) {
                int ci = i * 96 + tid;
                int ch = ci >> 2, off = ci & 3;
                cpa16(xsb + db + (uint32_t)(ch * XST2 + off * 2) * 8,
                      xg + ch * NPX + off * 2 + p);
            }
            if (tid < 44)
                cpa16(mmb + dm + (uint32_t)(mk * 8 + mo * 2) * 8,
                      mg + mk * NPX + mo * 2 + p);
            CP_COMMIT();
            CP_WAIT2();                      // stage hc complete
        } else if (hc + 1 < NST) {
            CP_WAIT1();
        } else {
            CP_WAIT0();
        }
        __syncthreads();
        const u64* xbuf = &xs[0][0] + (size_t)cur * (CB2 * XST2);
        const ulonglong2* xA = (const ulonglong2*)(xbuf + tid * XST2);
        const ulonglong2* xB = (const ulonglong2*)(xbuf + (tid + 96) * XST2);
        const u64* mc = &mm[0][0] + (size_t)cur * (KK * 8);
        #pragma unroll
        for (int j2 = 0; j2 < 4; j2++) {
            ulonglong2 va = xA[j2], vb = xB[j2];
            #pragma unroll
            for (int k = 0; k < KK; k++) {
                ulonglong2 mv = *(const ulonglong2*)(mc + k * 8 + j2 * 2);
                acc[k]      = fma2(va.x, mv.x, acc[k]);
                acc[k]      = fma2(va.y, mv.y, acc[k]);
                acc[KK + k] = fma2(vb.x, mv.x, acc[KK + k]);
                acc[KK + k] = fma2(vb.y, mv.y, acc[KK + k]);
            }
        }
        __syncthreads();                     // protect buf before restage
        cur = (cur == 2) ? 0 : cur + 1;
        stg = (stg == 2) ? 0 : stg + 1;
    }

    const int cA = c0 + tid, cB = cA + 96;
    float* pA = g_afp + ((size_t)(q * BB + b) * CC + cA) * KK;
    float* pB = g_afp + ((size_t)(q * BB + b) * CC + cB) * KK;
    #pragma unroll
    for (int k = 0; k < KK; k++) {
        float lo, hi;
        upk(acc[k], lo, hi);      pA[k] = lo + hi;
        upk(acc[KK + k], lo, hi); pB[k] = lo + hi;
    }
}

// ===== kernel 2fin: combine pixel-halves, modulate, afm + fsT + attn =======
// grid 384, block 256: one (b,c) per thread.
__global__ void __launch_bounds__(256) k2fin(const float* __restrict__ modulation,
                                             float* __restrict__ out_afm,
                                             float* __restrict__ out_attn) {
    const int idx = blockIdx.x * 256 + threadIdx.x;   // 0..98303
    const int b = idx / CC, c = idx - b * CC;
    const float* p0 = g_afp + (size_t)idx * KK;
    const float* p1 = g_afp + ((size_t)BB * CC + idx) * KK;
    const float* md = modulation + c * KK;
    float* ao = out_afm + (size_t)idx * KK;
    const float inv = 1.f / 784.f;
    float fs = 0.f;
    #pragma unroll
    for (int k = 0; k < KK; k++) {
        float v = (p0[k] + p1[k]) * inv * md[k];
        ao[k] = v;
        fs += v;
    }
    g_fsT[c * BB + b] = fs;
    if (idx < BB * KK) {                     // finish attn (g_attnp from k1)
        int ab = idx / KK, ak = idx - ab * KK;
        float t = 0.f;
        #pragma unroll
        for (int qq = 0; qq < NB1; qq++) t += g_attnp[(qq * BB + ab) * KK + ak];
        out_attn[idx] = t;
    }
}

// ===== kernel 3: score partials over c-quarters =============================
__global__ void __launch_bounds__(128) k_scores(const float* __restrict__ w_cls) {
    const int warp = threadIdx.x >> 5, lane = threadIdx.x & 31;
    const int tid = threadIdx.x;
    const int n0 = blockIdx.x * 4, q = blockIdx.y;
    __shared__ float fsm[256 * BB];           // 32 KB
    __shared__ float4 wsm[4][64];             // 4 KB

    float acc = 0.f;
    for (int ch = 0; ch < 3; ch++) {
        const int cbase = q * 768 + ch * 256;
        __syncthreads();
        const float4* src = (const float4*)(g_fsT + (size_t)cbase * BB);
        float4* dst = (float4*)fsm;
        #pragma unroll
        for (int i = 0; i < 16; i++)          // 2048 float4, coalesced, MLP 16
            dst[i * 128 + tid] = src[i * 128 + tid];
        #pragma unroll
        for (int i = 0; i < 2; i++) {
            int idx = i * 128 + tid;          // 0..255
            int g = idx >> 6, j = idx & 63;
            wsm[g][j] = *((const float4*)(w_cls + (size_t)(n0 + g) * CC + cbase) + j);
        }
        __syncthreads();
        #pragma unroll 8
        for (int j = 0; j < 64; j++) {
            float4 wv = wsm[warp][j];         // broadcast LDS.128
            int c = j * 4;
            acc = fmaf(fsm[(c + 0) * BB + lane], wv.x, acc);
            acc = fmaf(fsm[(c + 1) * BB + lane], wv.y, acc);
            acc = fmaf(fsm[(c + 2) * BB + lane], wv.z, acc);
            acc = fmaf(fsm[(c + 3) * BB + lane], wv.w, acc);
        }
    }
    g_sp[(q * BB + lane) * NCLS + n0 + warp] = acc;
}

// ===== kernel 4: finish scores (sum 4 quarters) ============================
__global__ void __launch_bounds__(256) k_fin(float* __restrict__ out_scores) {
    int i = blockIdx.x * 256 + threadIdx.x;   // 6400 elements, grid 25
    out_scores[i] = (g_sp[i] + g_sp[BB * NCLS + i])
                  + (g_sp[2 * BB * NCLS + i] + g_sp[3 * BB * NCLS + i]);
}

// ============================== launch =====================================
extern "C" void kernel_launch(void* const* d_in, const int* in_sizes, int n_in,
                              void* d_out, int out_size) {
    const float* x          = (const float*)d_in[0];
    const float* w_land     = (const float*)d_in[1];
    const float* modulation = (const float*)d_in[2];
    const float* w_cls      = (const float*)d_in[3];
    float* out        = (float*)d_out;
    float* out_afm    = out;                               // (B,C,K)  1081344
    float* out_scores = out + 1081344;                     // (B,NC)      6400
    float* out_maps   = out + 1087744;                     // (B,K,H,W) 275968
    float* out_attn   = out + 1363712;                     // (B,K)        352

    k_asq<<<KK, 256>>>(w_land);
    k_pack<<<24, 256>>>(w_land);
    k1<<<dim3(NB1, BB), 256>>>(x, out_maps);
    k2<<<dim3(CC / CB2, NQ, BB), 96>>>(x, out_maps);
    k2fin<<<384, 256>>>(modulation, out_afm, out_attn);
    k_scores<<<dim3(50, 4), 128>>>(w_cls);
    k_fin<<<25, 256>>>(out_scores);
}